// round 9
// baseline (speedup 1.0000x reference)
#include <cuda_runtime.h>
#include <cuda_bf16.h>

// Global scratch (zero-initialized at module load; reset by the last block
// every launch so each graph replay starts clean).
__device__ double        g_acc;
__device__ unsigned int  g_count;

// Row-owned formulation: each thread handles 4 rows = 12 floats = 3 float4
// loads per input array (6 front-batched LDG.128). This variant measured the
// lightest ALU (19.7%) and best DRAM% across 7 rounds of alternatives
// (smem transpose, 8-row MLP, element-parallel + shfl, persistent grid,
// evict-first streaming, L2 residency split) — all of which plateaued at
// 5.4-5.6 TB/s, the measured ceiling for a cold dual-read stream here.
__global__ void __launch_bounds__(512) range_loss_kernel(
    const float4* __restrict__ preds4,
    const float4* __restrict__ target4,
    float* __restrict__ out,
    double inv_count,
    unsigned int nblocks)
{
    const unsigned tid  = blockIdx.x * blockDim.x + threadIdx.x;
    const unsigned base = tid * 3u;   // float4 index; 3 float4 = 4 rows

    float4 p4a = preds4[base + 0];
    float4 p4b = preds4[base + 1];
    float4 p4c = preds4[base + 2];
    float4 t4a = target4[base + 0];
    float4 t4b = target4[base + 1];
    float4 t4c = target4[base + 2];

    float p[12], t[12];
    p[0]=p4a.x; p[1]=p4a.y; p[2]=p4a.z; p[3]=p4a.w;
    p[4]=p4b.x; p[5]=p4b.y; p[6]=p4b.z; p[7]=p4b.w;
    p[8]=p4c.x; p[9]=p4c.y; p[10]=p4c.z; p[11]=p4c.w;
    t[0]=t4a.x; t[1]=t4a.y; t[2]=t4a.z; t[3]=t4a.w;
    t[4]=t4b.x; t[5]=t4b.y; t[6]=t4b.z; t[7]=t4b.w;
    t[8]=t4c.x; t[9]=t4c.y; t[10]=t4c.z; t[11]=t4c.w;

    float acc = 0.0f;
    #pragma unroll
    for (int r = 0; r < 4; r++) {
        float p0 = p[3*r + 0], p1 = p[3*r + 1], p2 = p[3*r + 2];
        float t0 = t[3*r + 0], t1 = t[3*r + 1], t2 = t[3*r + 2];

        // Rewrites always set t <- p, so contribution is z ? 0 : (p-t)^2.
        if ((p0 < 0.1f && t0 == 0.0f) || (p0 > 0.9f && t0 == 1.0f)) t0 = p0;
        if ((p2 < 0.1f && t2 == 0.0f) || (p2 > 0.9f && t2 == 1.0f)) t2 = p2;
        // in_range: 1.02p > t && 0.98p < t  ==  |t - p| < 0.02p  (p > 0 here;
        // 1.0+RANGE / 1.0-RANGE round to exactly 1.02f / 0.98f in fp32, and
        // for p in (0,1), t in {0,1} the boundary sets have measure zero).
        bool in_range = fabsf(t1 - p1) < 0.02f * p1;
        if ((p2 > 0.9f) || in_range) t1 = p1;

        float d0 = p0 - t0;
        float d1 = p1 - t1;
        float d2 = p2 - t2;
        acc += d0 * d0 + d1 * d1 + d2 * d2;
    }

    // Warp reduction
    #pragma unroll
    for (int o = 16; o > 0; o >>= 1)
        acc += __shfl_xor_sync(0xffffffffu, acc, o);

    // Cross-warp reduction in shared memory (16 warps)
    __shared__ float warp_sums[16];
    const int lane = threadIdx.x & 31;
    const int wid  = threadIdx.x >> 5;
    if (lane == 0) warp_sums[wid] = acc;
    __syncthreads();

    if (wid == 0) {
        float v = (lane < 16) ? warp_sums[lane] : 0.0f;
        #pragma unroll
        for (int o = 8; o > 0; o >>= 1)
            v += __shfl_xor_sync(0xffffffffu, v, o);

        if (lane == 0) {
            atomicAdd(&g_acc, (double)v);
            __threadfence();
            unsigned int done = atomicAdd(&g_count, 1u);
            if (done == nblocks - 1u) {
                // Last block: read+reset accumulator atomically, write result,
                // reset counter for the next replay.
                unsigned long long raw =
                    atomicExch((unsigned long long*)&g_acc, 0ull);
                double total = __longlong_as_double(raw);
                out[0] = (float)(total * inv_count);
                atomicExch(&g_count, 0u);
            }
        }
    }
}

extern "C" void kernel_launch(void* const* d_in, const int* in_sizes, int n_in,
                              void* d_out, int out_size)
{
    const float4* preds4  = (const float4*)d_in[0];
    const float4* target4 = (const float4*)d_in[1];
    float* out = (float*)d_out;

    const long long nelem    = (long long)in_sizes[0];  // N * 3 = 25165824
    const long long nrows    = nelem / 3;               // 8388608
    const long long nthreads = nrows / 4;               // 4 rows / thread
    const int block = 512;
    const unsigned int grid = (unsigned int)((nthreads + block - 1) / block);

    range_loss_kernel<<<grid, block>>>(preds4, target4, out,
                                       1.0 / (double)nelem, grid);
}